// round 14
// baseline (speedup 1.0000x reference)
#include <cuda_runtime.h>
#include <cuda_fp16.h>
#include <math.h>
#include <stdint.h>

#define N_TOK  2048
#define DIMM   1024
#define HEADS  16
#define DHEAD  64
#define MF     64
#define CHUNK  64
#define NCHUNK 32   // 2048 / 64

// ---------------- scratch (__device__ globals; no allocations) ----------------
__device__ float g_q[N_TOK * DIMM];
__device__ float g_k[N_TOK * DIMM];
__device__ float g_v[N_TOK * DIMM];
__device__ float g_phiq[HEADS * N_TOK * MF];                 // [h][n][m]
__device__ float g_phik[HEADS * N_TOK * MF];
__device__ float g_Schunk[HEADS * NCHUNK * MF * DHEAD];      // [h][c][m][d]
__device__ float g_Spref[HEADS * NCHUNK * MF * DHEAD];
__device__ float g_ksum[HEADS * NCHUNK * MF];
__device__ float g_kpref[HEADS * NCHUNK * MF];

// precomputed fp16 operands
__device__ __half g_xh[N_TOK * DIMM];
__device__ __half g_xl[N_TOK * DIMM];
__device__ __half g_wqh[DIMM * DIMM];
__device__ __half g_wvh[DIMM * DIMM];
__device__ __half g_wkh[DIMM * DIMM];
__device__ __half g_wkl[DIMM * DIMM];
__device__ __half g_woh[DIMM * DIMM];
__device__ __half g_attnh[N_TOK * DIMM];                     // [n][h*64+d] fp16

// =====================================================================
// MMA helpers
// =====================================================================
__device__ __forceinline__ void mma_f16(float* d, const uint32_t* a, const uint32_t* b) {
    asm volatile(
        "mma.sync.aligned.m16n8k16.row.col.f32.f16.f16.f32 "
        "{%0,%1,%2,%3}, {%4,%5,%6,%7}, {%8,%9}, {%0,%1,%2,%3};\n"
        : "+f"(d[0]), "+f"(d[1]), "+f"(d[2]), "+f"(d[3])
        : "r"(a[0]), "r"(a[1]), "r"(a[2]), "r"(a[3]),
          "r"(b[0]), "r"(b[1]));
}
__device__ __forceinline__ uint32_t cvt_h2(float x, float y) {
    __half2 h = __float22half2_rn(make_float2(x, y));
    return *(uint32_t*)&h;
}
// split a float pair into fp16 hi + fp16 lo (packed half2 words)
__device__ __forceinline__ void split_h2(float x, float y, uint32_t& hi, uint32_t& lo) {
    __half2 h = __float22half2_rn(make_float2(x, y));
    float2 hf = __half22float2(h);
    __half2 l = __float22half2_rn(make_float2(x - hf.x, y - hf.y));
    hi = *(uint32_t*)&h;
    lo = *(uint32_t*)&l;
}

// ---------------- conversion pass --------------------------------------------
// seg 0: x -> xh, xl            (no scale)
// seg 1: wq*256 -> wqh ; seg 2: wv*256 -> wvh ; seg 4: wo*256 -> woh
// seg 3: wk*256 -> wkh, wkl
__global__ __launch_bounds__(256) void cvt_kernel(
    const float* __restrict__ x, const float* __restrict__ wq,
    const float* __restrict__ wv, const float* __restrict__ wk,
    const float* __restrict__ wo)
{
    const int seg = blockIdx.y;
    const size_t i4 = ((size_t)blockIdx.x * 256 + threadIdx.x) * 4;
    if (seg == 0) {
        float4 v = *(const float4*)(x + i4);
        uint32_t h01, l01, h23, l23;
        split_h2(v.x, v.y, h01, l01);
        split_h2(v.z, v.w, h23, l23);
        *(uint2*)&g_xh[i4] = make_uint2(h01, h23);
        *(uint2*)&g_xl[i4] = make_uint2(l01, l23);
    } else {
        if (i4 >= (size_t)DIMM * DIMM) return;
        const float* src = (seg == 1) ? wq : (seg == 2) ? wv : (seg == 3) ? wk : wo;
        float4 v = *(const float4*)(src + i4);
        v.x *= 256.f; v.y *= 256.f; v.z *= 256.f; v.w *= 256.f;
        if (seg == 3) {
            uint32_t h01, l01, h23, l23;
            split_h2(v.x, v.y, h01, l01);
            split_h2(v.z, v.w, h23, l23);
            *(uint2*)&g_wkh[i4] = make_uint2(h01, h23);
            *(uint2*)&g_wkl[i4] = make_uint2(l01, l23);
        } else {
            __half* dst = (seg == 1) ? g_wqh : (seg == 2) ? g_wvh : g_woh;
            *(uint2*)&dst[i4] = make_uint2(cvt_h2(v.x, v.y), cvt_h2(v.z, v.w));
        }
    }
}

#define K_ST 12   // half2 words per smem row (proven conflict-free layout)

// ---------- fp16 single-term GEMM, precomputed-half operands ------------------
// C[r,c] = sum_k A[r,k] * W[c,k] (+bias). 32-K stages = two 16-K halves.
// W was scaled by 256 at conversion; epilogue multiplies 1/256.
template<bool BIAS>
__device__ __forceinline__ void gemm_h_body(
    const __half* __restrict__ A, const __half* __restrict__ W,
    float* __restrict__ C, const float* __restrict__ bias,
    uint32_t (*sA)[128 * K_ST], uint32_t (*sB)[128 * K_ST])
{
    const int tid  = threadIdx.x;
    const int warp = tid >> 5, lane = tid & 31;
    const int wm = warp & 3, wn = warp >> 2;
    const int g = lane >> 2, t4 = lane & 3;
    const int rowBase = blockIdx.y * 128;
    const int colBase = blockIdx.x * 128;

    const int r0 = tid >> 2;          // 0..63 (rows r0, r0+64)
    const int q4 = (tid & 3) * 4;     // half k offset within a 16-K half
    const int cw = (tid & 3) * 2;     // half2 word col

    float acc[2][8][4];
#pragma unroll
    for (int i = 0; i < 2; i++)
#pragma unroll
        for (int j = 0; j < 8; j++)
#pragma unroll
            for (int c = 0; c < 4; c++) acc[i][j][c] = 0.f;

    uint2 pa[2][2], pb[2][2];         // [half][rowgroup]
#pragma unroll
    for (int hh = 0; hh < 2; hh++)
#pragma unroll
        for (int i = 0; i < 2; i++) {
            pa[hh][i] = *(const uint2*)(A + (size_t)(rowBase + r0 + 64 * i) * DIMM + 16 * hh + q4);
            pb[hh][i] = *(const uint2*)(W + (size_t)(colBase + r0 + 64 * i) * DIMM + 16 * hh + q4);
        }

    for (int kt = 0; kt < DIMM; kt += 32) {
#pragma unroll
        for (int hh = 0; hh < 2; hh++)
#pragma unroll
            for (int i = 0; i < 2; i++) {
                int off = (r0 + 64 * i) * K_ST + cw;
                *(uint2*)&sA[hh][off] = pa[hh][i];
                *(uint2*)&sB[hh][off] = pb[hh][i];
            }
        __syncthreads();
        if (kt + 32 < DIMM) {
#pragma unroll
            for (int hh = 0; hh < 2; hh++)
#pragma unroll
                for (int i = 0; i < 2; i++) {
                    pa[hh][i] = *(const uint2*)(A + (size_t)(rowBase + r0 + 64 * i) * DIMM + kt + 32 + 16 * hh + q4);
                    pb[hh][i] = *(const uint2*)(W + (size_t)(colBase + r0 + 64 * i) * DIMM + kt + 32 + 16 * hh + q4);
                }
        }
#pragma unroll
        for (int hh = 0; hh < 2; hh++) {
            uint32_t ah[2][4], bh[8][2];
#pragma unroll
            for (int i = 0; i < 2; i++) {
                int rr = (wm * 32 + i * 16 + g) * K_ST;
                ah[i][0] = sA[hh][rr + t4];
                ah[i][1] = sA[hh][rr + 8 * K_ST + t4];
                ah[i][2] = sA[hh][rr + t4 + 4];
                ah[i][3] = sA[hh][rr + 8 * K_ST + t4 + 4];
            }
#pragma unroll
            for (int j = 0; j < 8; j++) {
                int rr = (wn * 64 + j * 8 + g) * K_ST;
                bh[j][0] = sB[hh][rr + t4];
                bh[j][1] = sB[hh][rr + t4 + 4];
            }
#pragma unroll
            for (int i = 0; i < 2; i++)
#pragma unroll
                for (int j = 0; j < 8; j++)
                    mma_f16(acc[i][j], ah[i], bh[j]);
        }
        __syncthreads();
    }

    const float inv = 1.f / 256.f;
#pragma unroll
    for (int i = 0; i < 2; i++)
#pragma unroll
        for (int j = 0; j < 8; j++) {
            int row = rowBase + wm * 32 + i * 16 + g;
            int col = colBase + wn * 64 + j * 8 + t4 * 2;
            float2 v0 = make_float2(acc[i][j][0] * inv, acc[i][j][1] * inv);
            float2 v1 = make_float2(acc[i][j][2] * inv, acc[i][j][3] * inv);
            if (BIAS) {
                v0.x += bias[col]; v0.y += bias[col + 1];
                v1.x += bias[col]; v1.y += bias[col + 1];
            }
            *(float2*)(C + (size_t)row * DIMM + col) = v0;
            *(float2*)(C + (size_t)(row + 8) * DIMM + col) = v1;
        }
}

__global__ __launch_bounds__(256) void qv_mma_kernel()
{
    __shared__ __align__(16) uint32_t sA[2][128 * K_ST];
    __shared__ __align__(16) uint32_t sB[2][128 * K_ST];
    if (blockIdx.z == 0) gemm_h_body<false>(g_xh, g_wqh, g_q, nullptr, sA, sB);
    else                 gemm_h_body<false>(g_xh, g_wvh, g_v, nullptr, sA, sB);
}
__global__ __launch_bounds__(256) void out_mma_kernel(
    const float* __restrict__ bo, float* __restrict__ out)
{
    __shared__ __align__(16) uint32_t sA[2][128 * K_ST];
    __shared__ __align__(16) uint32_t sB[2][128 * K_ST];
    gemm_h_body<true>(g_attnh, g_woh, out, bo, sA, sB);
}

// ---------- fp16 3-term split GEMM for k (fp32-accurate), precomputed ---------
#define K_KC 16

__global__ __launch_bounds__(256) void k_mma_kernel()
{
    __shared__ __align__(16) uint32_t sAh[128 * K_ST];
    __shared__ __align__(16) uint32_t sAl[128 * K_ST];
    __shared__ __align__(16) uint32_t sBh[128 * K_ST];
    __shared__ __align__(16) uint32_t sBl[128 * K_ST];
    const int tid  = threadIdx.x;
    const int warp = tid >> 5, lane = tid & 31;
    const int wm = warp & 3, wn = warp >> 2;
    const int g = lane >> 2, t4 = lane & 3;
    const int rowBase = blockIdx.y * 128;
    const int colBase = blockIdx.x * 128;

    const int r0 = tid >> 2;          // 0..63 (rows r0, r0+64)
    const int q4 = (tid & 3) * 4;     // half k offset
    const int cw = (tid & 3) * 2;     // half2 word col

    float acc[2][8][4];
#pragma unroll
    for (int i = 0; i < 2; i++)
#pragma unroll
        for (int j = 0; j < 8; j++)
#pragma unroll
            for (int c = 0; c < 4; c++) acc[i][j][c] = 0.f;

    uint2 pah[2], pal[2], pbh[2], pbl[2];
#pragma unroll
    for (int i = 0; i < 2; i++) {
        size_t ra = (size_t)(rowBase + r0 + 64 * i) * DIMM + q4;
        size_t rb = (size_t)(colBase + r0 + 64 * i) * DIMM + q4;
        pah[i] = *(const uint2*)(g_xh + ra);
        pal[i] = *(const uint2*)(g_xl + ra);
        pbh[i] = *(const uint2*)(g_wkh + rb);
        pbl[i] = *(const uint2*)(g_wkl + rb);
    }

    for (int kt = 0; kt < DIMM; kt += K_KC) {
#pragma unroll
        for (int i = 0; i < 2; i++) {
            int off = (r0 + 64 * i) * K_ST + cw;
            *(uint2*)&sAh[off] = pah[i];
            *(uint2*)&sAl[off] = pal[i];
            *(uint2*)&sBh[off] = pbh[i];
            *(uint2*)&sBl[off] = pbl[i];
        }
        __syncthreads();
        if (kt + K_KC < DIMM) {
#pragma unroll
            for (int i = 0; i < 2; i++) {
                size_t ra = (size_t)(rowBase + r0 + 64 * i) * DIMM + kt + K_KC + q4;
                size_t rb = (size_t)(colBase + r0 + 64 * i) * DIMM + kt + K_KC + q4;
                pah[i] = *(const uint2*)(g_xh + ra);
                pal[i] = *(const uint2*)(g_xl + ra);
                pbh[i] = *(const uint2*)(g_wkh + rb);
                pbl[i] = *(const uint2*)(g_wkl + rb);
            }
        }
        uint32_t ah[2][4], al[2][4], bh[8][2], bl[8][2];
#pragma unroll
        for (int i = 0; i < 2; i++) {
            int rr = (wm * 32 + i * 16 + g) * K_ST;
            ah[i][0] = sAh[rr + t4];
            ah[i][1] = sAh[rr + 8 * K_ST + t4];
            ah[i][2] = sAh[rr + t4 + 4];
            ah[i][3] = sAh[rr + 8 * K_ST + t4 + 4];
            al[i][0] = sAl[rr + t4];
            al[i][1] = sAl[rr + 8 * K_ST + t4];
            al[i][2] = sAl[rr + t4 + 4];
            al[i][3] = sAl[rr + 8 * K_ST + t4 + 4];
        }
#pragma unroll
        for (int j = 0; j < 8; j++) {
            int rr = (wn * 64 + j * 8 + g) * K_ST;
            bh[j][0] = sBh[rr + t4];
            bh[j][1] = sBh[rr + t4 + 4];
            bl[j][0] = sBl[rr + t4];
            bl[j][1] = sBl[rr + t4 + 4];
        }
#pragma unroll
        for (int i = 0; i < 2; i++)
#pragma unroll
            for (int j = 0; j < 8; j++) {
                mma_f16(acc[i][j], ah[i], bh[j]);
                mma_f16(acc[i][j], ah[i], bl[j]);
                mma_f16(acc[i][j], al[i], bh[j]);
            }
        __syncthreads();
    }

    const float inv = 1.f / 256.f;
#pragma unroll
    for (int i = 0; i < 2; i++)
#pragma unroll
        for (int j = 0; j < 8; j++) {
            int row = rowBase + wm * 32 + i * 16 + g;
            int col = colBase + wn * 64 + j * 8 + t4 * 2;
            *(float2*)(g_k + (size_t)row * DIMM + col) =
                make_float2(acc[i][j][0] * inv, acc[i][j][1] * inv);
            *(float2*)(g_k + (size_t)(row + 8) * DIMM + col) =
                make_float2(acc[i][j][2] * inv, acc[i][j][3] * inv);
        }
}

// ---------------- phi: phi = exp(q@omega^T - 0.5||q||^2) / sqrt(M) ----------
__global__ __launch_bounds__(256) void phi_kernel(const float* __restrict__ omega)
{
    __shared__ __align__(16) float soT[64 * 68];  // [d][m] transposed
    __shared__ __align__(16) float sx[16 * 64];   // [t][d]
    const int tid = threadIdx.x;
    const int h = blockIdx.y;
    const int n0 = blockIdx.x * 16;
    const float* X = (blockIdx.z == 0) ? g_q : g_k;
    float* PHI = (blockIdx.z == 0) ? g_phiq : g_phik;

#pragma unroll
    for (int i = 0; i < 16; i++) {
        int o = tid + 256 * i;
        soT[(o & 63) * 68 + (o >> 6)] = omega[o];   // soT[d][m] = omega[m][d]
    }
#pragma unroll
    for (int i = 0; i < 4; i++) {
        int o = tid + 256 * i;
        sx[o] = X[(size_t)(n0 + (o >> 6)) * DIMM + h * 64 + (o & 63)];
    }
    __syncthreads();

    const int t = tid >> 4;
    const int m0 = (tid & 15) * 4;
    float p0 = 0.f, p1 = 0.f, p2 = 0.f, p3 = 0.f, nrm = 0.f;
#pragma unroll
    for (int d = 0; d < 64; d++) {
        float xv = sx[t * 64 + d];
        float4 om = *(const float4*)&soT[d * 68 + m0];
        p0 = fmaf(xv, om.x, p0); p1 = fmaf(xv, om.y, p1);
        p2 = fmaf(xv, om.z, p2); p3 = fmaf(xv, om.w, p3);
        nrm = fmaf(xv, xv, nrm);
    }
    nrm *= 0.5f;
    float4 o;
    o.x = expf(p0 - nrm) * 0.125f;
    o.y = expf(p1 - nrm) * 0.125f;
    o.z = expf(p2 - nrm) * 0.125f;
    o.w = expf(p3 - nrm) * 0.125f;
    *(float4*)&PHI[((size_t)h * N_TOK + n0 + t) * MF + m0] = o;
}

// ---------------- per-chunk stats: S_c = phik^T @ v ; ksum_c ------------------
__global__ __launch_bounds__(256) void chunk_stats_kernel()
{
    __shared__ __align__(16) float sp[64 * 64];   // phik [t][m]
    __shared__ __align__(16) float sv[64 * 64];   // v    [t][d]
    const int tid = threadIdx.x;
    const int c = blockIdx.x, h = blockIdx.y;
    const size_t pbase = ((size_t)h * N_TOK + c * 64) * MF;

#pragma unroll
    for (int i = 0; i < 16; i++) {
        int o = tid + 256 * i;
        sp[o] = g_phik[pbase + o];
        sv[o] = g_v[(size_t)(c * 64 + (o >> 6)) * DIMM + h * 64 + (o & 63)];
    }
    __syncthreads();

    const int m0 = (tid >> 4) * 4;
    const int d0 = (tid & 15) * 4;
    float4 acc[4];
    float ks[4];
#pragma unroll
    for (int i = 0; i < 4; i++) { acc[i] = make_float4(0.f, 0.f, 0.f, 0.f); ks[i] = 0.f; }

#pragma unroll 4
    for (int t = 0; t < 64; t++) {
        float4 p = *(const float4*)&sp[t * 64 + m0];
        float4 vv = *(const float4*)&sv[t * 64 + d0];
        acc[0].x = fmaf(p.x, vv.x, acc[0].x); acc[0].y = fmaf(p.x, vv.y, acc[0].y);
        acc[0].z = fmaf(p.x, vv.z, acc[0].z); acc[0].w = fmaf(p.x, vv.w, acc[0].w);
        acc[1].x = fmaf(p.y, vv.x, acc[1].x); acc[1].y = fmaf(p.y, vv.y, acc[1].y);
        acc[1].z = fmaf(p.y, vv.z, acc[1].z); acc[1].w = fmaf(p.y, vv.w, acc[1].w);
        acc[2].x = fmaf(p.z, vv.x, acc[2].x); acc[2].y = fmaf(p.z, vv.y, acc[2].y);
        acc[2].z = fmaf(p.z, vv.z, acc[2].z); acc[2].w = fmaf(p.z, vv.w, acc[2].w);
        acc[3].x = fmaf(p.w, vv.x, acc[3].x); acc[3].y = fmaf(p.w, vv.y, acc[3].y);
        acc[3].z = fmaf(p.w, vv.z, acc[3].z); acc[3].w = fmaf(p.w, vv.w, acc[3].w);
        ks[0] += p.x; ks[1] += p.y; ks[2] += p.z; ks[3] += p.w;
    }

    const size_t sbase = (size_t)(h * NCHUNK + c) * 4096;
#pragma unroll
    for (int i = 0; i < 4; i++)
        *(float4*)&g_Schunk[sbase + (size_t)(m0 + i) * 64 + d0] = acc[i];
    if ((tid & 15) == 0) {
#pragma unroll
        for (int i = 0; i < 4; i++)
            g_ksum[(h * NCHUNK + c) * 64 + m0 + i] = ks[i];
    }
}

// ---------------- exclusive prefix over chunks per head -----------------------
__global__ __launch_bounds__(256) void prefix_kernel()
{
    const int h = blockIdx.y;
    const int slice = blockIdx.x;
    const int tid = threadIdx.x;
    if (slice < 4) {
        const int o4 = slice * 256 + tid;   // float4 index within 1024
        const float4* src = (const float4*)g_Schunk + (size_t)h * NCHUNK * 1024 + o4;
        float4* dst = (float4*)g_Spref + (size_t)h * NCHUNK * 1024 + o4;
        float4 acc = make_float4(0.f, 0.f, 0.f, 0.f);
        float4 nxt = src[0];
#pragma unroll
        for (int c = 0; c < NCHUNK; c++) {
            float4 cur = nxt;
            if (c + 1 < NCHUNK) nxt = src[(size_t)(c + 1) * 1024];
            dst[(size_t)c * 1024] = acc;
            acc.x += cur.x; acc.y += cur.y; acc.z += cur.z; acc.w += cur.w;
        }
    } else if (tid < 64) {
        const int base = h * NCHUNK * 64 + tid;
        float acc = 0.f;
        float nxt = g_ksum[base];
#pragma unroll
        for (int c = 0; c < NCHUNK; c++) {
            float cur = nxt;
            if (c + 1 < NCHUNK) nxt = g_ksum[base + (c + 1) * 64];
            g_kpref[base + c * 64] = acc;
            acc += cur;
        }
    }
}

// ---------------- intra-chunk causal attention --------------------------------
// out = phiq@Spref + tril(phiq@phik^T)@v ; z = phiq.kpref + rowsum(tril(A))
#define IST 68
__global__ __launch_bounds__(256) void intra_kernel()
{
    __shared__ __align__(16) float bufA[64 * IST]; // phiqT[m][n] -> A[t][n]
    __shared__ __align__(16) float bufB[64 * IST]; // Spref[m][d] -> phikT[m][t] -> v[t][d]
    __shared__ float sks[64];
    const int tid = threadIdx.x;
    const int c = blockIdx.x, h = blockIdx.y;
    const size_t pbase = ((size_t)h * N_TOK + c * 64) * MF;
    const size_t sbase = (size_t)(h * NCHUNK + c) * 4096;

    const int n0 = (tid >> 4) * 4;
    const int d0 = (tid & 15) * 4;

    // stage 1: phiqT (transposed) + Spref + kpref
#pragma unroll
    for (int i = 0; i < 16; i++) {
        int o = tid + 256 * i;
        bufA[(o & 63) * IST + (o >> 6)] = g_phiq[pbase + o];        // [m][n]
        bufB[(o >> 6) * IST + (o & 63)] = g_Spref[sbase + o];       // [m][d]
    }
    if (tid < 64) sks[tid] = g_kpref[(h * NCHUNK + c) * 64 + tid];
    __syncthreads();

    // loop1: acc = phiq @ Spref ; zn = phiq . kpref
    float4 acc[4];
    float zn[4];
#pragma unroll
    for (int i = 0; i < 4; i++) { acc[i] = make_float4(0.f, 0.f, 0.f, 0.f); zn[i] = 0.f; }
#pragma unroll 4
    for (int m = 0; m < 64; m++) {
        float4 q = *(const float4*)&bufA[m * IST + n0];
        float4 s = *(const float4*)&bufB[m * IST + d0];
        float kp = sks[m];
        acc[0].x = fmaf(q.x, s.x, acc[0].x); acc[0].y = fmaf(q.x, s.y, acc[0].y);
        acc[0].z = fmaf(q.x, s.z, acc[0].z); acc[0].w = fmaf(q.x, s.w, acc[0].w);
        acc[1].x = fmaf(q.y, s.x, acc[1].x); acc[1].y = fmaf(q.y, s.y, acc[1].y);
        acc[1].z = fmaf(q.y, s.z, acc[1].z); acc[1].w = fmaf(q.y, s.w, acc[1].w);
        acc[2].x = fmaf(q.z, s.x, acc[2].x); acc[2].y = fmaf(q.z, s.y, acc[2].y);
        acc[2].z = fmaf(q.z, s.z, acc[2].z); acc[2].w = fmaf(q.z, s.w, acc[2].w);
        acc[3].x = fmaf(q.w, s.x, acc[3].x); acc[3].y = fmaf(q.w, s.y, acc[3].y);
        acc[3].z = fmaf(q.w, s.z, acc[3].z); acc[3].w = fmaf(q.w, s.w, acc[3].w);
        zn[0] = fmaf(q.x, kp, zn[0]); zn[1] = fmaf(q.y, kp, zn[1]);
        zn[2] = fmaf(q.z, kp, zn[2]); zn[3] = fmaf(q.w, kp, zn[3]);
    }
    __syncthreads();

    // stage 2: phikT into bufB
#pragma unroll
    for (int i = 0; i < 16; i++) {
        int o = tid + 256 * i;
        bufB[(o & 63) * IST + (o >> 6)] = g_phik[pbase + o];        // [m][t]
    }
    __syncthreads();

    // loop2: rA[t][n] = sum_m phik[t][m] * phiq[n][m]
    const int t0 = (tid >> 4) * 4;
    const int na0 = (tid & 15) * 4;
    float4 rA[4];   // rA[ti] = A[t0+ti][na0..na0+3]
#pragma unroll
    for (int i = 0; i < 4; i++) rA[i] = make_float4(0.f, 0.f, 0.f, 0.f);
#pragma unroll 4
    for (int m = 0; m < 64; m++) {
        float4 kk = *(const float4*)&bufB[m * IST + t0];
        float4 qq = *(const float4*)&bufA[m * IST + na0];
        rA[0].x = fmaf(kk.x, qq.x, rA[0].x); rA[0].y = fmaf(kk.x, qq.y, rA[0].y);
        rA[0].z = fmaf(kk.x, qq.z, rA[0].z); rA[0].w = fmaf(kk.x, qq.w, rA[0].w);
        rA[1].x = fmaf(kk.y, qq.x, rA[1].x); rA[1].y = fmaf(kk.y, qq.y, rA[1].y);
        rA[1].z = fmaf(kk.y, qq.z, rA[1].z); rA[1].w = fmaf(kk.y, qq.w, rA[1].w);
        rA[2].x = fmaf(kk.z, qq.x, rA[2].x); rA[2].y = fmaf(kk.z, qq.y, rA[2].y);
        rA[2].z = fmaf(kk.z, qq.z, rA[2].z); rA[2].w = fmaf(kk.z, qq.w, rA[2].w);
        rA[3].x = fmaf(kk.w, qq.x, rA[3].x); rA[3].y = fmaf(kk.w, qq.y, rA[3].y);
        rA[3].z = fmaf(kk.w, qq.z, rA[3].z); rA[3].w = fmaf(kk.w, qq.w, rA[3].w);
    }
    __syncthreads();   // all reads of bufA/bufB complete

    // stage 3: A -> bufA[t][n] ; v -> bufB[t][d]
#pragma unroll
    for (int i = 0; i < 4; i++)
        *(float4*)&bufA[(t0 + i) * IST + na0] = rA[i];
#pragma unroll
    for (int i = 0; i < 16; i++) {
        int o = tid + 256 * i;
        bufB[(o >> 6) * IST + (o & 63)] =
            g_v[(size_t)(c * 64 + (o >> 6)) * DIMM + h * 64 + (o & 63)];
    }
    __syncthreads();

    // loop3: acc += tril(A) @ v ; zn += causal rowsum(A)
    for (int t = 0; t < n0; t++) {
        float4 a = *(const float4*)&bufA[t * IST + n0];
        float4 vv = *(const float4*)&bufB[t * IST + d0];
        acc[0].x = fmaf(a.x, vv.x, acc[0].x); acc[0].y = fmaf(a.x, vv.y, acc[0].y);
        acc[0].z = fmaf(a.x, vv.z, acc[0].z); acc[0].w = fmaf(a.x, vv.w, acc[0].w);
        acc[1].x = fmaf(a.y, vv.x, acc[1].x); acc[1].y = fmaf(a.y, vv.y, acc[1].y);
        acc[1].z = fmaf(a.y, vv.z, acc[1].z); acc[1].w = fmaf(a.y, vv.w, acc[1].w);
        acc[2].x = fmaf(a.z, vv.x, acc[2].x); acc[2].y = fmaf(a.z, vv.y, acc[2].y);
        acc[2].z = fmaf(a.z, vv.z, acc[2].z); acc[2].w = fmaf(a.z, vv.w, acc[2].w);
        acc[3].x = fmaf(a.w, vv.x, acc[3].x); acc[3].y = fmaf(a.w, vv.y, acc[3].y);
        acc[3].z = fmaf(a.w, vv.z, acc[3].z); acc[3].w = fmaf(a.w, vv.w, acc[3].w);
        zn[0] += a.x; zn[1] += a.y; zn[2] += a.z; zn[3] += a.w;
    }
#pragma unroll
    for (int e = 0; e < 4; e++) {       // edge rows t = n0..n0+3, mask t <= n
        int t = n0 + e;
        float4 a = *(const float4*)&bufA[t * IST + n0];
        float4 vv = *(const float4*)&bufB[t * IST + d0];
        float w0 = (e <= 0) ? a.x : 0.f;
        float w1 = (e <= 1) ? a.y : 0.f;
        float w2 = (e <= 2) ? a.z : 0.f;
        float w3 = a.w;
        acc[0].x = fmaf(w0, vv.x, acc[0].x); acc[0].y = fmaf(w0, vv.y, acc[0].y);
        acc[0].z = fmaf(w0, vv.z, acc[0].z); acc[0].w = fmaf(w0, vv.w, acc[0].w);
        acc[1].x = fmaf(w1, vv.x, acc[1].x); acc[1].y = fmaf(w1, vv.y, acc[1].y);
        acc[1].z = fmaf(w1, vv.z, acc[1].z); acc[1].w = fmaf(w1, vv.w, acc[1].w);
        acc[2].x = fmaf(w2, vv.x, acc[2].x); acc[2].y = fmaf(w2, vv.y, acc[2].y);
        acc[2].z = fmaf(w2, vv.z, acc[2].z); acc[2].w = fmaf(w2, vv.w, acc[2].w);
        acc[3].x = fmaf(w3, vv.x, acc[3].x); acc[3].y = fmaf(w3, vv.y, acc[3].y);
        acc[3].z = fmaf(w3, vv.z, acc[3].z); acc[3].w = fmaf(w3, vv.w, acc[3].w);
        zn[0] += w0; zn[1] += w1; zn[2] += w2; zn[3] += w3;
    }

    // scale by 1/(z + eps) and store as fp16 (same rounding point as the
    // out-GEMM's former in-kernel conversion — bit-identical downstream)
#pragma unroll
    for (int i = 0; i < 4; i++) {
        float zi = 1.f / (zn[i] + 1e-6f);
        float4 o = acc[i];
        o.x *= zi; o.y *= zi; o.z *= zi; o.w *= zi;
        *(uint2*)&g_attnh[(size_t)(c * 64 + n0 + i) * DIMM + h * 64 + d0] =
            make_uint2(cvt_h2(o.x, o.y), cvt_h2(o.z, o.w));
    }
}

// ---------------- launch ------------------------------------------------------
extern "C" void kernel_launch(void* const* d_in, const int* in_sizes, int n_in,
                              void* d_out, int out_size)
{
    const float* x     = (const float*)d_in[0];
    const float* omega = (const float*)d_in[1];
    const float* wq    = (const float*)d_in[2];
    const float* wk    = (const float*)d_in[3];
    const float* wv    = (const float*)d_in[4];
    const float* wo    = (const float*)d_in[5];
    const float* bo    = (const float*)d_in[6];
    float* out = (float*)d_out;

    cvt_kernel<<<dim3(N_TOK * DIMM / 1024, 5), 256>>>(x, wq, wv, wk, wo);
    qv_mma_kernel<<<dim3(DIMM / 128, N_TOK / 128, 2), 256>>>();
    k_mma_kernel<<<dim3(DIMM / 128, N_TOK / 128), 256>>>();
    phi_kernel<<<dim3(N_TOK / 16, HEADS, 2), 256>>>(omega);
    chunk_stats_kernel<<<dim3(NCHUNK, HEADS), 256>>>();
    prefix_kernel<<<dim3(5, HEADS), 256>>>();
    intra_kernel<<<dim3(NCHUNK, HEADS), 256>>>();
    out_mma_kernel<<<dim3(DIMM / 128, N_TOK / 128), 256>>>(bo, out);
}

// round 15
// speedup vs baseline: 1.1414x; 1.1414x over previous
#include <cuda_runtime.h>
#include <cuda_fp16.h>
#include <math.h>
#include <stdint.h>

#define N_TOK  2048
#define DIMM   1024
#define HEADS  16
#define DHEAD  64
#define MF     64
#define CHUNK  64
#define NCHUNK 32   // 2048 / 64

// ---------------- scratch (__device__ globals; no allocations) ----------------
__device__ float g_q[N_TOK * DIMM];
__device__ float g_k[N_TOK * DIMM];
__device__ float g_v[N_TOK * DIMM];
__device__ float g_phiq[HEADS * N_TOK * MF];                 // [h][n][m]
__device__ float g_phik[HEADS * N_TOK * MF];
__device__ float g_Schunk[HEADS * NCHUNK * MF * DHEAD];      // [h][c][m][d]
__device__ float g_Spref[HEADS * NCHUNK * MF * DHEAD];
__device__ float g_ksum[HEADS * NCHUNK * MF];
__device__ float g_kpref[HEADS * NCHUNK * MF];
__device__ float g_attn[N_TOK * DIMM];                       // [n][h*64+d]

// =====================================================================
// MMA helpers
// =====================================================================
__device__ __forceinline__ void mma_f16(float* d, const uint32_t* a, const uint32_t* b) {
    asm volatile(
        "mma.sync.aligned.m16n8k16.row.col.f32.f16.f16.f32 "
        "{%0,%1,%2,%3}, {%4,%5,%6,%7}, {%8,%9}, {%0,%1,%2,%3};\n"
        : "+f"(d[0]), "+f"(d[1]), "+f"(d[2]), "+f"(d[3])
        : "r"(a[0]), "r"(a[1]), "r"(a[2]), "r"(a[3]),
          "r"(b[0]), "r"(b[1]));
}
__device__ __forceinline__ uint32_t cvt_h2(float x, float y) {
    __half2 h = __float22half2_rn(make_float2(x, y));
    return *(uint32_t*)&h;
}
// split a float pair into fp16 hi + fp16 lo (packed half2 words)
__device__ __forceinline__ void split_h2(float x, float y, uint32_t& hi, uint32_t& lo) {
    __half2 h = __float22half2_rn(make_float2(x, y));
    float2 hf = __half22float2(h);
    __half2 l = __float22half2_rn(make_float2(x - hf.x, y - hf.y));
    hi = *(uint32_t*)&h;
    lo = *(uint32_t*)&l;
}

#define K_ST 12   // half2 words per smem row (proven conflict-free layout)

// ---------- fp16 single-term GEMM (tf32-class precision) ----------------------
// C[r,c] = sum_k A[r,k] * W[c,k] (+bias). 32-K stages = two 16-K halves,
// each half uses the proven K_ST=12 layout. W scaled by 256, epilogue 1/256.
template<bool BIAS>
__device__ __forceinline__ void gemm_f16s_body(
    const float* __restrict__ A, const float* __restrict__ W,
    float* __restrict__ C, const float* __restrict__ bias,
    uint32_t (*sA)[128 * K_ST], uint32_t (*sB)[128 * K_ST])
{
    const int tid  = threadIdx.x;
    const int warp = tid >> 5, lane = tid & 31;
    const int wm = warp & 3, wn = warp >> 2;
    const int g = lane >> 2, t4 = lane & 3;
    const int rowBase = blockIdx.y * 128;
    const int colBase = blockIdx.x * 128;

    const int r0 = tid >> 2;          // 0..63 (rows r0, r0+64)
    const int q4 = (tid & 3) * 4;     // float k offset within a 16-K half
    const int cw = (tid & 3) * 2;     // half2 word col

    float acc[2][8][4];
#pragma unroll
    for (int i = 0; i < 2; i++)
#pragma unroll
        for (int j = 0; j < 8; j++)
#pragma unroll
            for (int c = 0; c < 4; c++) acc[i][j][c] = 0.f;

    float4 pa[2][2], pb[2][2];        // [half][rowgroup]
#pragma unroll
    for (int hh = 0; hh < 2; hh++)
#pragma unroll
        for (int i = 0; i < 2; i++) {
            pa[hh][i] = *(const float4*)(A + (size_t)(rowBase + r0 + 64 * i) * DIMM + 16 * hh + q4);
            pb[hh][i] = *(const float4*)(W + (size_t)(colBase + r0 + 64 * i) * DIMM + 16 * hh + q4);
        }

    for (int kt = 0; kt < DIMM; kt += 32) {
#pragma unroll
        for (int hh = 0; hh < 2; hh++)
#pragma unroll
            for (int i = 0; i < 2; i++) {
                float4 a = pa[hh][i], b = pb[hh][i];
                b.x *= 256.f; b.y *= 256.f; b.z *= 256.f; b.w *= 256.f;
                int off = (r0 + 64 * i) * K_ST + cw;
                *(uint2*)&sA[hh][off] = make_uint2(cvt_h2(a.x, a.y), cvt_h2(a.z, a.w));
                *(uint2*)&sB[hh][off] = make_uint2(cvt_h2(b.x, b.y), cvt_h2(b.z, b.w));
            }
        __syncthreads();
        if (kt + 32 < DIMM) {
#pragma unroll
            for (int hh = 0; hh < 2; hh++)
#pragma unroll
                for (int i = 0; i < 2; i++) {
                    pa[hh][i] = *(const float4*)(A + (size_t)(rowBase + r0 + 64 * i) * DIMM + kt + 32 + 16 * hh + q4);
                    pb[hh][i] = *(const float4*)(W + (size_t)(colBase + r0 + 64 * i) * DIMM + kt + 32 + 16 * hh + q4);
                }
        }
#pragma unroll
        for (int hh = 0; hh < 2; hh++) {
            uint32_t ah[2][4], bh[8][2];
#pragma unroll
            for (int i = 0; i < 2; i++) {
                int rr = (wm * 32 + i * 16 + g) * K_ST;
                ah[i][0] = sA[hh][rr + t4];
                ah[i][1] = sA[hh][rr + 8 * K_ST + t4];
                ah[i][2] = sA[hh][rr + t4 + 4];
                ah[i][3] = sA[hh][rr + 8 * K_ST + t4 + 4];
            }
#pragma unroll
            for (int j = 0; j < 8; j++) {
                int rr = (wn * 64 + j * 8 + g) * K_ST;
                bh[j][0] = sB[hh][rr + t4];
                bh[j][1] = sB[hh][rr + t4 + 4];
            }
#pragma unroll
            for (int i = 0; i < 2; i++)
#pragma unroll
                for (int j = 0; j < 8; j++)
                    mma_f16(acc[i][j], ah[i], bh[j]);
        }
        __syncthreads();
    }

    const float inv = 1.f / 256.f;
#pragma unroll
    for (int i = 0; i < 2; i++)
#pragma unroll
        for (int j = 0; j < 8; j++) {
            int row = rowBase + wm * 32 + i * 16 + g;
            int col = colBase + wn * 64 + j * 8 + t4 * 2;
            float2 v0 = make_float2(acc[i][j][0] * inv, acc[i][j][1] * inv);
            float2 v1 = make_float2(acc[i][j][2] * inv, acc[i][j][3] * inv);
            if (BIAS) {
                v0.x += bias[col]; v0.y += bias[col + 1];
                v1.x += bias[col]; v1.y += bias[col + 1];
            }
            *(float2*)(C + (size_t)row * DIMM + col) = v0;
            *(float2*)(C + (size_t)(row + 8) * DIMM + col) = v1;
        }
}

__global__ __launch_bounds__(256) void qv_mma_kernel(
    const float* __restrict__ x, const float* __restrict__ wq,
    const float* __restrict__ wv)
{
    __shared__ __align__(16) uint32_t sA[2][128 * K_ST];
    __shared__ __align__(16) uint32_t sB[2][128 * K_ST];
    if (blockIdx.z == 0) gemm_f16s_body<false>(x, wq, g_q, nullptr, sA, sB);
    else                 gemm_f16s_body<false>(x, wv, g_v, nullptr, sA, sB);
}
__global__ __launch_bounds__(256) void out_mma_kernel(
    const float* __restrict__ wo, const float* __restrict__ bo,
    float* __restrict__ out)
{
    __shared__ __align__(16) uint32_t sA[2][128 * K_ST];
    __shared__ __align__(16) uint32_t sB[2][128 * K_ST];
    gemm_f16s_body<true>(g_attn, wo, out, bo, sA, sB);
}

// ---------- fp16 3-term split GEMM for k (fp32-accurate) — R10-proven ---------
#define K_KC 16

__global__ __launch_bounds__(256) void k_mma_kernel(
    const float* __restrict__ x, const float* __restrict__ wk)
{
    __shared__ __align__(16) uint32_t sAh[128 * K_ST];
    __shared__ __align__(16) uint32_t sAl[128 * K_ST];
    __shared__ __align__(16) uint32_t sBh[128 * K_ST];
    __shared__ __align__(16) uint32_t sBl[128 * K_ST];
    const int tid  = threadIdx.x;
    const int warp = tid >> 5, lane = tid & 31;
    const int wm = warp & 3, wn = warp >> 2;
    const int g = lane >> 2, t4 = lane & 3;
    const int rowBase = blockIdx.y * 128;
    const int colBase = blockIdx.x * 128;

    const int r0 = tid >> 2;          // 0..63 (rows r0, r0+64)
    const int q4 = (tid & 3) * 4;     // float k offset
    const int cw = (tid & 3) * 2;     // half2 word col

    float acc[2][8][4];
#pragma unroll
    for (int i = 0; i < 2; i++)
#pragma unroll
        for (int j = 0; j < 8; j++)
#pragma unroll
            for (int c = 0; c < 4; c++) acc[i][j][c] = 0.f;

    float4 pa[2], pb[2];
#pragma unroll
    for (int i = 0; i < 2; i++) {
        pa[i] = *(const float4*)(x  + (size_t)(rowBase + r0 + 64 * i) * DIMM + q4);
        pb[i] = *(const float4*)(wk + (size_t)(colBase + r0 + 64 * i) * DIMM + q4);
    }

    for (int kt = 0; kt < DIMM; kt += K_KC) {
#pragma unroll
        for (int i = 0; i < 2; i++) {
            float4 a = pa[i], b = pb[i];
            // scale B by 2^8 so its lo-term stays fp16-normal
            b.x *= 256.f; b.y *= 256.f; b.z *= 256.f; b.w *= 256.f;
            uint32_t ah01, al01, ah23, al23, bh01, bl01, bh23, bl23;
            split_h2(a.x, a.y, ah01, al01);
            split_h2(a.z, a.w, ah23, al23);
            split_h2(b.x, b.y, bh01, bl01);
            split_h2(b.z, b.w, bh23, bl23);
            int off = (r0 + 64 * i) * K_ST + cw;
            *(uint2*)&sAh[off] = make_uint2(ah01, ah23);
            *(uint2*)&sAl[off] = make_uint2(al01, al23);
            *(uint2*)&sBh[off] = make_uint2(bh01, bh23);
            *(uint2*)&sBl[off] = make_uint2(bl01, bl23);
        }
        __syncthreads();
        if (kt + K_KC < DIMM) {
#pragma unroll
            for (int i = 0; i < 2; i++) {
                pa[i] = *(const float4*)(x  + (size_t)(rowBase + r0 + 64 * i) * DIMM + kt + K_KC + q4);
                pb[i] = *(const float4*)(wk + (size_t)(colBase + r0 + 64 * i) * DIMM + kt + K_KC + q4);
            }
        }
        uint32_t ah[2][4], al[2][4], bh[8][2], bl[8][2];
#pragma unroll
        for (int i = 0; i < 2; i++) {
            int rr = (wm * 32 + i * 16 + g) * K_ST;
            ah[i][0] = sAh[rr + t4];
            ah[i][1] = sAh[rr + 8 * K_ST + t4];
            ah[i][2] = sAh[rr + t4 + 4];
            ah[i][3] = sAh[rr + 8 * K_ST + t4 + 4];
            al[i][0] = sAl[rr + t4];
            al[i][1] = sAl[rr + 8 * K_ST + t4];
            al[i][2] = sAl[rr + t4 + 4];
            al[i][3] = sAl[rr + 8 * K_ST + t4 + 4];
        }
#pragma unroll
        for (int j = 0; j < 8; j++) {
            int rr = (wn * 64 + j * 8 + g) * K_ST;
            bh[j][0] = sBh[rr + t4];
            bh[j][1] = sBh[rr + t4 + 4];
            bl[j][0] = sBl[rr + t4];
            bl[j][1] = sBl[rr + t4 + 4];
        }
#pragma unroll
        for (int i = 0; i < 2; i++)
#pragma unroll
            for (int j = 0; j < 8; j++) {
                mma_f16(acc[i][j], ah[i], bh[j]);
                mma_f16(acc[i][j], ah[i], bl[j]);
                mma_f16(acc[i][j], al[i], bh[j]);
            }
        __syncthreads();
    }

    const float inv = 1.f / 256.f;
#pragma unroll
    for (int i = 0; i < 2; i++)
#pragma unroll
        for (int j = 0; j < 8; j++) {
            int row = rowBase + wm * 32 + i * 16 + g;
            int col = colBase + wn * 64 + j * 8 + t4 * 2;
            *(float2*)(g_k + (size_t)row * DIMM + col) =
                make_float2(acc[i][j][0] * inv, acc[i][j][1] * inv);
            *(float2*)(g_k + (size_t)(row + 8) * DIMM + col) =
                make_float2(acc[i][j][2] * inv, acc[i][j][3] * inv);
        }
}

// ---------------- phi: phi = exp(q@omega^T - 0.5||q||^2) / sqrt(M) ----------
// __expf: FMUL + MUFU.EX2 only — strips accurate-expf's range-reduction
// overhead; MUFU count (the hard floor) is unchanged.
__global__ __launch_bounds__(256) void phi_kernel(const float* __restrict__ omega)
{
    __shared__ __align__(16) float soT[64 * 68];  // [d][m] transposed
    __shared__ __align__(16) float sx[16 * 64];   // [t][d]
    const int tid = threadIdx.x;
    const int h = blockIdx.y;
    const int n0 = blockIdx.x * 16;
    const float* X = (blockIdx.z == 0) ? g_q : g_k;
    float* PHI = (blockIdx.z == 0) ? g_phiq : g_phik;

#pragma unroll
    for (int i = 0; i < 16; i++) {
        int o = tid + 256 * i;
        soT[(o & 63) * 68 + (o >> 6)] = omega[o];   // soT[d][m] = omega[m][d]
    }
#pragma unroll
    for (int i = 0; i < 4; i++) {
        int o = tid + 256 * i;
        sx[o] = X[(size_t)(n0 + (o >> 6)) * DIMM + h * 64 + (o & 63)];
    }
    __syncthreads();

    const int t = tid >> 4;
    const int m0 = (tid & 15) * 4;
    float p0 = 0.f, p1 = 0.f, p2 = 0.f, p3 = 0.f, nrm = 0.f;
#pragma unroll
    for (int d = 0; d < 64; d++) {
        float xv = sx[t * 64 + d];
        float4 om = *(const float4*)&soT[d * 68 + m0];
        p0 = fmaf(xv, om.x, p0); p1 = fmaf(xv, om.y, p1);
        p2 = fmaf(xv, om.z, p2); p3 = fmaf(xv, om.w, p3);
        nrm = fmaf(xv, xv, nrm);
    }
    nrm *= 0.5f;
    float4 o;
    o.x = __expf(p0 - nrm) * 0.125f;
    o.y = __expf(p1 - nrm) * 0.125f;
    o.z = __expf(p2 - nrm) * 0.125f;
    o.w = __expf(p3 - nrm) * 0.125f;
    *(float4*)&PHI[((size_t)h * N_TOK + n0 + t) * MF + m0] = o;
}

// ---------------- per-chunk stats: S_c = phik^T @ v ; ksum_c ------------------
__global__ __launch_bounds__(256) void chunk_stats_kernel()
{
    __shared__ __align__(16) float sp[64 * 64];   // phik [t][m]
    __shared__ __align__(16) float sv[64 * 64];   // v    [t][d]
    const int tid = threadIdx.x;
    const int c = blockIdx.x, h = blockIdx.y;
    const size_t pbase = ((size_t)h * N_TOK + c * 64) * MF;

#pragma unroll
    for (int i = 0; i < 16; i++) {
        int o = tid + 256 * i;
        sp[o] = g_phik[pbase + o];
        sv[o] = g_v[(size_t)(c * 64 + (o >> 6)) * DIMM + h * 64 + (o & 63)];
    }
    __syncthreads();

    const int m0 = (tid >> 4) * 4;
    const int d0 = (tid & 15) * 4;
    float4 acc[4];
    float ks[4];
#pragma unroll
    for (int i = 0; i < 4; i++) { acc[i] = make_float4(0.f, 0.f, 0.f, 0.f); ks[i] = 0.f; }

#pragma unroll 4
    for (int t = 0; t < 64; t++) {
        float4 p = *(const float4*)&sp[t * 64 + m0];
        float4 vv = *(const float4*)&sv[t * 64 + d0];
        acc[0].x = fmaf(p.x, vv.x, acc[0].x); acc[0].y = fmaf(p.x, vv.y, acc[0].y);
        acc[0].z = fmaf(p.x, vv.z, acc[0].z); acc[0].w = fmaf(p.x, vv.w, acc[0].w);
        acc[1].x = fmaf(p.y, vv.x, acc[1].x); acc[1].y = fmaf(p.y, vv.y, acc[1].y);
        acc[1].z = fmaf(p.y, vv.z, acc[1].z); acc[1].w = fmaf(p.y, vv.w, acc[1].w);
        acc[2].x = fmaf(p.z, vv.x, acc[2].x); acc[2].y = fmaf(p.z, vv.y, acc[2].y);
        acc[2].z = fmaf(p.z, vv.z, acc[2].z); acc[2].w = fmaf(p.z, vv.w, acc[2].w);
        acc[3].x = fmaf(p.w, vv.x, acc[3].x); acc[3].y = fmaf(p.w, vv.y, acc[3].y);
        acc[3].z = fmaf(p.w, vv.z, acc[3].z); acc[3].w = fmaf(p.w, vv.w, acc[3].w);
        ks[0] += p.x; ks[1] += p.y; ks[2] += p.z; ks[3] += p.w;
    }

    const size_t sbase = (size_t)(h * NCHUNK + c) * 4096;
#pragma unroll
    for (int i = 0; i < 4; i++)
        *(float4*)&g_Schunk[sbase + (size_t)(m0 + i) * 64 + d0] = acc[i];
    if ((tid & 15) == 0) {
#pragma unroll
        for (int i = 0; i < 4; i++)
            g_ksum[(h * NCHUNK + c) * 64 + m0 + i] = ks[i];
    }
}

// ---------------- exclusive prefix over chunks per head -----------------------
__global__ __launch_bounds__(256) void prefix_kernel()
{
    const int h = blockIdx.y;
    const int slice = blockIdx.x;
    const int tid = threadIdx.x;
    if (slice < 4) {
        const int o4 = slice * 256 + tid;   // float4 index within 1024
        const float4* src = (const float4*)g_Schunk + (size_t)h * NCHUNK * 1024 + o4;
        float4* dst = (float4*)g_Spref + (size_t)h * NCHUNK * 1024 + o4;
        float4 acc = make_float4(0.f, 0.f, 0.f, 0.f);
        float4 nxt = src[0];
#pragma unroll
        for (int c = 0; c < NCHUNK; c++) {
            float4 cur = nxt;
            if (c + 1 < NCHUNK) nxt = src[(size_t)(c + 1) * 1024];
            dst[(size_t)c * 1024] = acc;
            acc.x += cur.x; acc.y += cur.y; acc.z += cur.z; acc.w += cur.w;
        }
    } else if (tid < 64) {
        const int base = h * NCHUNK * 64 + tid;
        float acc = 0.f;
        float nxt = g_ksum[base];
#pragma unroll
        for (int c = 0; c < NCHUNK; c++) {
            float cur = nxt;
            if (c + 1 < NCHUNK) nxt = g_ksum[base + (c + 1) * 64];
            g_kpref[base + c * 64] = acc;
            acc += cur;
        }
    }
}

// ---------------- intra-chunk causal attention --------------------------------
// out = phiq@Spref + tril(phiq@phik^T)@v ; z = phiq.kpref + rowsum(tril(A))
#define IST 68
__global__ __launch_bounds__(256) void intra_kernel()
{
    __shared__ __align__(16) float bufA[64 * IST]; // phiqT[m][n] -> A[t][n]
    __shared__ __align__(16) float bufB[64 * IST]; // Spref[m][d] -> phikT[m][t] -> v[t][d]
    __shared__ float sks[64];
    const int tid = threadIdx.x;
    const int c = blockIdx.x, h = blockIdx.y;
    const size_t pbase = ((size_t)h * N_TOK + c * 64) * MF;
    const size_t sbase = (size_t)(h * NCHUNK + c) * 4096;

    const int n0 = (tid >> 4) * 4;
    const int d0 = (tid & 15) * 4;

    // stage 1: phiqT (transposed) + Spref + kpref
#pragma unroll
    for (int i = 0; i < 16; i++) {
        int o = tid + 256 * i;
        bufA[(o & 63) * IST + (o >> 6)] = g_phiq[pbase + o];        // [m][n]
        bufB[(o >> 6) * IST + (o & 63)] = g_Spref[sbase + o];       // [m][d]
    }
    if (tid < 64) sks[tid] = g_kpref[(h * NCHUNK + c) * 64 + tid];
    __syncthreads();

    // loop1: acc = phiq @ Spref ; zn = phiq . kpref
    float4 acc[4];
    float zn[4];
#pragma unroll
    for (int i = 0; i < 4; i++) { acc[i] = make_float4(0.f, 0.f, 0.f, 0.f); zn[i] = 0.f; }
#pragma unroll 4
    for (int m = 0; m < 64; m++) {
        float4 q = *(const float4*)&bufA[m * IST + n0];
        float4 s = *(const float4*)&bufB[m * IST + d0];
        float kp = sks[m];
        acc[0].x = fmaf(q.x, s.x, acc[0].x); acc[0].y = fmaf(q.x, s.y, acc[0].y);
        acc[0].z = fmaf(q.x, s.z, acc[0].z); acc[0].w = fmaf(q.x, s.w, acc[0].w);
        acc[1].x = fmaf(q.y, s.x, acc[1].x); acc[1].y = fmaf(q.y, s.y, acc[1].y);
        acc[1].z = fmaf(q.y, s.z, acc[1].z); acc[1].w = fmaf(q.y, s.w, acc[1].w);
        acc[2].x = fmaf(q.z, s.x, acc[2].x); acc[2].y = fmaf(q.z, s.y, acc[2].y);
        acc[2].z = fmaf(q.z, s.z, acc[2].z); acc[2].w = fmaf(q.z, s.w, acc[2].w);
        acc[3].x = fmaf(q.w, s.x, acc[3].x); acc[3].y = fmaf(q.w, s.y, acc[3].y);
        acc[3].z = fmaf(q.w, s.z, acc[3].z); acc[3].w = fmaf(q.w, s.w, acc[3].w);
        zn[0] = fmaf(q.x, kp, zn[0]); zn[1] = fmaf(q.y, kp, zn[1]);
        zn[2] = fmaf(q.z, kp, zn[2]); zn[3] = fmaf(q.w, kp, zn[3]);
    }
    __syncthreads();

    // stage 2: phikT into bufB
#pragma unroll
    for (int i = 0; i < 16; i++) {
        int o = tid + 256 * i;
        bufB[(o & 63) * IST + (o >> 6)] = g_phik[pbase + o];        // [m][t]
    }
    __syncthreads();

    // loop2: rA[t][n] = sum_m phik[t][m] * phiq[n][m]
    const int t0 = (tid >> 4) * 4;
    const int na0 = (tid & 15) * 4;
    float4 rA[4];   // rA[ti] = A[t0+ti][na0..na0+3]
#pragma unroll
    for (int i = 0; i < 4; i++) rA[i] = make_float4(0.f, 0.f, 0.f, 0.f);
#pragma unroll 4
    for (int m = 0; m < 64; m++) {
        float4 kk = *(const float4*)&bufB[m * IST + t0];
        float4 qq = *(const float4*)&bufA[m * IST + na0];
        rA[0].x = fmaf(kk.x, qq.x, rA[0].x); rA[0].y = fmaf(kk.x, qq.y, rA[0].y);
        rA[0].z = fmaf(kk.x, qq.z, rA[0].z); rA[0].w = fmaf(kk.x, qq.w, rA[0].w);
        rA[1].x = fmaf(kk.y, qq.x, rA[1].x); rA[1].y = fmaf(kk.y, qq.y, rA[1].y);
        rA[1].z = fmaf(kk.y, qq.z, rA[1].z); rA[1].w = fmaf(kk.y, qq.w, rA[1].w);
        rA[2].x = fmaf(kk.z, qq.x, rA[2].x); rA[2].y = fmaf(kk.z, qq.y, rA[2].y);
        rA[2].z = fmaf(kk.z, qq.z, rA[2].z); rA[2].w = fmaf(kk.z, qq.w, rA[2].w);
        rA[3].x = fmaf(kk.w, qq.x, rA[3].x); rA[3].y = fmaf(kk.w, qq.y, rA[3].y);
        rA[3].z = fmaf(kk.w, qq.z, rA[3].z); rA[3].w = fmaf(kk.w, qq.w, rA[3].w);
    }
    __syncthreads();   // all reads of bufA/bufB complete

    // stage 3: A -> bufA[t][n] ; v -> bufB[t][d]
#pragma unroll
    for (int i = 0; i < 4; i++)
        *(float4*)&bufA[(t0 + i) * IST + na0] = rA[i];
#pragma unroll
    for (int i = 0; i < 16; i++) {
        int o = tid + 256 * i;
        bufB[(o >> 6) * IST + (o & 63)] =
            g_v[(size_t)(c * 64 + (o >> 6)) * DIMM + h * 64 + (o & 63)];
    }
    __syncthreads();

    // loop3: acc += tril(A) @ v ; zn += causal rowsum(A)
    for (int t = 0; t < n0; t++) {
        float4 a = *(const float4*)&bufA[t * IST + n0];
        float4 vv = *(const float4*)&bufB[t * IST + d0];
        acc[0].x = fmaf(a.x, vv.x, acc[0].x); acc[0].y = fmaf(a.x, vv.y, acc[0].y);
        acc[0].z = fmaf(a.x, vv.z, acc[0].z); acc[0].w = fmaf(a.x, vv.w, acc[0].w);
        acc[1].x = fmaf(a.y, vv.x, acc[1].x); acc[1].y = fmaf(a.y, vv.y, acc[1].y);
        acc[1].z = fmaf(a.y, vv.z, acc[1].z); acc[1].w = fmaf(a.y, vv.w, acc[1].w);
        acc[2].x = fmaf(a.z, vv.x, acc[2].x); acc[2].y = fmaf(a.z, vv.y, acc[2].y);
        acc[2].z = fmaf(a.z, vv.z, acc[2].z); acc[2].w = fmaf(a.z, vv.w, acc[2].w);
        acc[3].x = fmaf(a.w, vv.x, acc[3].x); acc[3].y = fmaf(a.w, vv.y, acc[3].y);
        acc[3].z = fmaf(a.w, vv.z, acc[3].z); acc[3].w = fmaf(a.w, vv.w, acc[3].w);
        zn[0] += a.x; zn[1] += a.y; zn[2] += a.z; zn[3] += a.w;
    }
#pragma unroll
    for (int e = 0; e < 4; e++) {       // edge rows t = n0..n0+3, mask t <= n
        int t = n0 + e;
        float4 a = *(const float4*)&bufA[t * IST + n0];
        float4 vv = *(const float4*)&bufB[t * IST + d0];
        float w0 = (e <= 0) ? a.x : 0.f;
        float w1 = (e <= 1) ? a.y : 0.f;
        float w2 = (e <= 2) ? a.z : 0.f;
        float w3 = a.w;
        acc[0].x = fmaf(w0, vv.x, acc[0].x); acc[0].y = fmaf(w0, vv.y, acc[0].y);
        acc[0].z = fmaf(w0, vv.z, acc[0].z); acc[0].w = fmaf(w0, vv.w, acc[0].w);
        acc[1].x = fmaf(w1, vv.x, acc[1].x); acc[1].y = fmaf(w1, vv.y, acc[1].y);
        acc[1].z = fmaf(w1, vv.z, acc[1].z); acc[1].w = fmaf(w1, vv.w, acc[1].w);
        acc[2].x = fmaf(w2, vv.x, acc[2].x); acc[2].y = fmaf(w2, vv.y, acc[2].y);
        acc[2].z = fmaf(w2, vv.z, acc[2].z); acc[2].w = fmaf(w2, vv.w, acc[2].w);
        acc[3].x = fmaf(w3, vv.x, acc[3].x); acc[3].y = fmaf(w3, vv.y, acc[3].y);
        acc[3].z = fmaf(w3, vv.z, acc[3].z); acc[3].w = fmaf(w3, vv.w, acc[3].w);
        zn[0] += w0; zn[1] += w1; zn[2] += w2; zn[3] += w3;
    }

    // scale by 1/(z + eps) and store
#pragma unroll
    for (int i = 0; i < 4; i++) {
        float zi = 1.f / (zn[i] + 1e-6f);
        float4 o = acc[i];
        o.x *= zi; o.y *= zi; o.z *= zi; o.w *= zi;
        *(float4*)&g_attn[(size_t)(c * 64 + n0 + i) * DIMM + h * 64 + d0] = o;
    }
}

// ---------------- launch ------------------------------------------------------
extern "C" void kernel_launch(void* const* d_in, const int* in_sizes, int n_in,
                              void* d_out, int out_size)
{
    const float* x     = (const float*)d_in[0];
    const float* omega = (const float*)d_in[1];
    const float* wq    = (const float*)d_in[2];
    const float* wk    = (const float*)d_in[3];
    const float* wv    = (const float*)d_in[4];
    const float* wv_   = wv;
    const float* wo    = (const float*)d_in[5];
    const float* bo    = (const float*)d_in[6];
    float* out = (float*)d_out;
    (void)wv_;

    qv_mma_kernel<<<dim3(DIMM / 128, N_TOK / 128, 2), 256>>>(x, wq, wv);
    k_mma_kernel<<<dim3(DIMM / 128, N_TOK / 128), 256>>>(x, wk);
    phi_kernel<<<dim3(N_TOK / 16, HEADS, 2), 256>>>(omega);
    chunk_stats_kernel<<<dim3(NCHUNK, HEADS), 256>>>();
    prefix_kernel<<<dim3(5, HEADS), 256>>>();
    intra_kernel<<<dim3(NCHUNK, HEADS), 256>>>();
    out_mma_kernel<<<dim3(DIMM / 128, N_TOK / 128), 256>>>(wo, bo, out);
}